// round 1
// baseline (speedup 1.0000x reference)
#include <cuda_runtime.h>

#define BATCH 2
#define NBOX  1000
#define NCLS  80
#define NCAND 100
#define SORTN 1024
#define FINAL_N 8192

// Scratch (static device allocations — allowed)
__device__ float              g_scores[BATCH * NCLS * NBOX];
__device__ float4             g_boxes [BATCH * NCLS * NBOX];
__device__ unsigned long long g_cand_keys [BATCH * NCLS * NCAND];
__device__ float4             g_cand_boxes[BATCH * NCLS * NCAND];

// ---------------------------------------------------------------------------
// Kernel A: softmax + box decode.  One warp per (b, n).
// ---------------------------------------------------------------------------
__global__ void decode_kernel(const float* __restrict__ cls,
                              const float* __restrict__ box,
                              const float* __restrict__ anc,
                              const float* __restrict__ info) {
    int gw   = (blockIdx.x * blockDim.x + threadIdx.x) >> 5;
    int lane = threadIdx.x & 31;
    if (gw >= BATCH * NBOX) return;
    int b = gw / NBOX, n = gw % NBOX;

    const float* lg = cls + (size_t)(b * NBOX + n) * 81;

    float mx = -1e30f;
    for (int c = lane; c < 81; c += 32) mx = fmaxf(mx, lg[c]);
    #pragma unroll
    for (int o = 16; o; o >>= 1) mx = fmaxf(mx, __shfl_xor_sync(0xffffffffu, mx, o));

    float s = 0.f;
    for (int c = lane; c < 81; c += 32) s += expf(lg[c] - mx);
    #pragma unroll
    for (int o = 16; o; o >>= 1) s += __shfl_xor_sync(0xffffffffu, s, o);
    float inv = 1.f / s;

    float4 a  = *(const float4*)(anc + (size_t)(b * NBOX + n) * 4);
    float ha  = a.z - a.x + 1.f;
    float wa  = a.w - a.y + 1.f;
    float cya = a.x + 0.5f * ha;
    float cxa = a.y + 0.5f * wa;
    float hmax = info[b * 5 + 0] - 1.f;
    float wmax = info[b * 5 + 1] - 1.f;

    for (int cc = 1 + lane; cc <= 80; cc += 32) {
        float p  = expf(lg[cc] - mx) * inv;
        float4 e = *(const float4*)(box + ((size_t)(b * NBOX + n) * 81 + cc) * 4);
        float dy = e.x / 10.f, dx = e.y / 10.f;
        float dh = e.z / 5.f,  dw = e.w / 5.f;
        float cy = dy * ha + cya;
        float cx = dx * wa + cxa;
        float h  = expf(dh) * ha;
        float w  = expf(dw) * wa;
        float ymin = fminf(fmaxf(cy - 0.5f * h,       0.f), hmax);
        float ymax = fminf(fmaxf(cy + 0.5f * h - 1.f, 0.f), hmax);
        float xmin = fminf(fmaxf(cx - 0.5f * w,       0.f), wmax);
        float xmax = fminf(fmaxf(cx + 0.5f * w - 1.f, 0.f), wmax);
        int ci = b * NCLS + (cc - 1);
        g_scores[ci * NBOX + n] = p;
        g_boxes [ci * NBOX + n] = make_float4(ymin, xmin, ymax, xmax);
    }
}

// ---------------------------------------------------------------------------
// Bitonic sort, 1024 u64 keys in SMEM, descending, one element per thread.
// ---------------------------------------------------------------------------
__device__ __forceinline__ void bitonic_1024_desc(unsigned long long* keys, int tid) {
    for (unsigned k = 2; k <= SORTN; k <<= 1) {
        for (unsigned j = k >> 1; j > 0; j >>= 1) {
            __syncthreads();
            unsigned ixj = tid ^ j;
            if (ixj > (unsigned)tid) {
                unsigned long long va = keys[tid];
                unsigned long long vb = keys[ixj];
                bool desc = ((tid & k) == 0);
                if (desc ? (va < vb) : (va > vb)) {
                    keys[tid] = vb;
                    keys[ixj] = va;
                }
            }
        }
    }
    __syncthreads();
}

// ---------------------------------------------------------------------------
// Kernel B: per (b,c) — sort 1000 scores, greedy NMS, per-class top-100.
// 160 blocks x 1024 threads.
// ---------------------------------------------------------------------------
__global__ __launch_bounds__(1024) void sort_nms_kernel() {
    __shared__ unsigned long long keys[SORTN];
    __shared__ float4 sbox[SORTN];
    __shared__ int    supp[SORTN];

    int tid = threadIdx.x;
    int b   = blockIdx.x / NCLS;
    int c   = blockIdx.x % NCLS;
    int ci  = b * NCLS + c;

    // key = (score_bits << 32) | ~orig_idx  -> desc sort == stable top_k
    unsigned long long k0 = 0ull;
    if (tid < NBOX) {
        float sc = g_scores[ci * NBOX + tid];
        k0 = ((unsigned long long)__float_as_uint(sc) << 32) | (unsigned)(~tid);
    }
    keys[tid] = k0;
    bitonic_1024_desc(keys, tid);

    // Gather boxes into SMEM in rank order
    float4 bx = make_float4(0.f, 0.f, 0.f, 0.f);
    if (tid < NBOX) {
        unsigned orig = ~(unsigned)keys[tid];
        bx = g_boxes[ci * NBOX + orig];
    }
    sbox[tid] = bx;
    supp[tid] = (tid < NBOX) ? 0 : 1;
    __syncthreads();

    // Greedy NMS (reference-equivalent)
    float4 bj = sbox[tid];
    float  aj = (bj.z - bj.x) * (bj.w - bj.y);
    for (int i = 0; i < NBOX; i++) {
        if (!supp[i]) {                 // uniform (SMEM, post-sync)
            if (tid > i && tid < NBOX && !supp[tid]) {
                float4 bi = sbox[i];
                float ai  = (bi.z - bi.x) * (bi.w - bi.y);
                float iy  = fmaxf(0.f, fminf(bi.z, bj.z) - fmaxf(bi.x, bj.x));
                float ix  = fmaxf(0.f, fminf(bi.w, bj.w) - fmaxf(bi.y, bj.y));
                float inter = iy * ix;
                float uni   = ai + aj - inter;
                float iou   = inter / fmaxf(uni, 1e-8f);
                if (iou > 0.5f) supp[tid] = 1;
            }
        }
        __syncthreads();
    }

    // Rebuild keys: zero suppressed scores, low bits = ~rank; re-sort.
    // This IS the per-class top-100 with reference zero/tie semantics.
    unsigned long long kk = keys[tid];
    __syncthreads();
    if (tid < NBOX) {
        unsigned long long hi = supp[tid] ? 0ull : (kk & 0xFFFFFFFF00000000ull);
        keys[tid] = hi | (unsigned)(~tid);
    } else {
        keys[tid] = 0ull;
    }
    bitonic_1024_desc(keys, tid);

    if (tid < NCAND) {
        unsigned long long kv = keys[tid];
        unsigned r = ~(unsigned)kv;           // rank within class (< 1000)
        int s = c * NCAND + tid;              // compact slot; order-isomorphic to flat idx
        g_cand_keys [b * NCLS * NCAND + s] =
            (kv & 0xFFFFFFFF00000000ull) | (unsigned)(~s);
        g_cand_boxes[b * NCLS * NCAND + s] = sbox[r];
    }
}

// ---------------------------------------------------------------------------
// Kernel C: global top-100 per batch. 2 blocks x 1024 threads, 64KB dyn SMEM.
// ---------------------------------------------------------------------------
__global__ __launch_bounds__(1024) void final_topk_kernel(float* __restrict__ out) {
    extern __shared__ unsigned long long sk[];   // FINAL_N keys
    int tid = threadIdx.x;
    int b   = blockIdx.x;

    for (int t = tid; t < FINAL_N; t += 1024)
        sk[t] = (t < NCLS * NCAND) ? g_cand_keys[b * NCLS * NCAND + t] : 0ull;

    for (unsigned k = 2; k <= FINAL_N; k <<= 1) {
        for (unsigned j = k >> 1; j > 0; j >>= 1) {
            __syncthreads();
            for (int t = tid; t < FINAL_N; t += 1024) {
                unsigned ixj = (unsigned)t ^ j;
                if (ixj > (unsigned)t) {
                    unsigned long long va = sk[t];
                    unsigned long long vb = sk[ixj];
                    bool desc = ((t & k) == 0);
                    if (desc ? (va < vb) : (va > vb)) {
                        sk[t]   = vb;
                        sk[ixj] = va;
                    }
                }
            }
        }
    }
    __syncthreads();

    if (tid < NCAND) {
        unsigned long long kv = sk[tid];
        float score = __uint_as_float((unsigned)(kv >> 32));
        unsigned s  = ~(unsigned)kv;              // compact slot (< 8000)
        float4 bx   = g_cand_boxes[b * NCLS * NCAND + s];
        float  cls  = (float)(s / NCAND + 1);
        float* o = out + (size_t)(b * NCAND + tid) * 6;
        o[0] = bx.x; o[1] = bx.y; o[2] = bx.z; o[3] = bx.w;
        o[4] = score; o[5] = cls;
    }
}

// ---------------------------------------------------------------------------
extern "C" void kernel_launch(void* const* d_in, const int* in_sizes, int n_in,
                              void* d_out, int out_size) {
    const float* cls  = (const float*)d_in[0];  // (B, N, 81)
    const float* box  = (const float*)d_in[1];  // (B, N, 324)
    const float* anc  = (const float*)d_in[2];  // (B, N, 4)
    const float* info = (const float*)d_in[3];  // (B, 5)

    decode_kernel<<<(BATCH * NBOX * 32 + 255) / 256, 256>>>(cls, box, anc, info);
    sort_nms_kernel<<<BATCH * NCLS, 1024>>>();

    cudaFuncSetAttribute(final_topk_kernel,
                         cudaFuncAttributeMaxDynamicSharedMemorySize,
                         FINAL_N * sizeof(unsigned long long));
    final_topk_kernel<<<BATCH, 1024, FINAL_N * sizeof(unsigned long long)>>>(
        (float*)d_out);
}